// round 5
// baseline (speedup 1.0000x reference)
#include <cuda_runtime.h>
#include <cuda_bf16.h>
#include <cstdint>

// Problem constants
#define N_NODES 50000
#define N_EDGES 640000
#define R_REL   8
#define NW1     1152           // (R+1)*128
#define NW2     640            // (R+1)*64 = 576 padded to 640
#define KTOT    384            // [Ah|Al|Ah] split-bf16 K
#define MT      391            // ceil(50000/128)
#define NBKT    (MT * R_REL)   // 3128

#define BM 128
#define BN 128
#define BK 64

// ---------------------------------------------------------------------------
// Device scratch
__device__ float         g_h1[(long long)N_NODES * 128];
__device__ float         g_h2[(long long)N_NODES * 64];
__device__ int           g_cnt[R_REL * N_NODES];
__device__ __nv_bfloat16 g_A[(long long)N_NODES * KTOT];
__device__ __nv_bfloat16 g_B1[NW1 * KTOT];
__device__ __nv_bfloat16 g_B2[NW2 * KTOT];
__device__ int           g_bkt[NBKT];      // bucket sizes
__device__ int           g_boff[NBKT];     // bucket start offsets
__device__ int           g_bcur[NBKT];     // fill cursors
__device__ uint2         g_epack[N_EDGES]; // {dst|(src&127)<<16, f32bits(w)}

__device__ __forceinline__ uint32_t smem_u32(const void* p) {
    uint32_t a;
    asm("{ .reg .u64 t; cvta.to.shared.u64 t, %1; cvt.u32.u64 %0, t; }" : "=r"(a) : "l"(p));
    return a;
}
__device__ __forceinline__ void cp16(uint32_t dst, const void* src, int src_sz) {
    asm volatile("cp.async.cg.shared.global [%0], [%1], 16, %2;"
                 :: "r"(dst), "l"(src), "r"(src_sz));
}

union BF4 { __nv_bfloat16 b[4]; uint2 u; };

// ---------------------------------------------------------------------------
// (1) histogram, 4 edges/thread for MLP
__global__ void count_kernel(const int* __restrict__ src, const int* __restrict__ dst,
                             const int* __restrict__ etype) {
    int e0 = (blockIdx.x * blockDim.x + threadIdx.x) * 4;
    if (e0 >= N_EDGES) return;
    int t[4], d[4], s[4];
#pragma unroll
    for (int q = 0; q < 4; q++) {
        t[q] = etype[e0 + q]; d[q] = dst[e0 + q]; s[q] = src[e0 + q];
    }
#pragma unroll
    for (int q = 0; q < 4; q++) {
        atomicAdd(&g_cnt[t[q] * N_NODES + d[q]], 1);
        atomicAdd(&g_bkt[(s[q] >> 7) * R_REL + t[q]], 1);
    }
}

// (2) exclusive scan over NBKT buckets (single block, 1024 thr x 4)
__global__ void scan_kernel() {
    __shared__ int tsum[1024];
    int tid = threadIdx.x;
    int base = tid * 4;
    int v[4]; int s = 0;
#pragma unroll
    for (int q = 0; q < 4; q++) {
        v[q] = (base + q < NBKT) ? g_bkt[base + q] : 0;
        s += v[q];
    }
    tsum[tid] = s;
    __syncthreads();
    for (int off = 1; off < 1024; off <<= 1) {
        int t = (tid >= off) ? tsum[tid - off] : 0;
        __syncthreads();
        tsum[tid] += t;
        __syncthreads();
    }
    int ex = tsum[tid] - s;
#pragma unroll
    for (int q = 0; q < 4; q++) {
        if (base + q < NBKT) { g_boff[base + q] = ex; g_bcur[base + q] = ex; }
        ex += v[q];
    }
}

// (3) bucket-sorted packed edge array, 4 edges/thread
__global__ void fill_kernel(const int* __restrict__ src, const int* __restrict__ dst,
                            const int* __restrict__ etype) {
    int e0 = (blockIdx.x * blockDim.x + threadIdx.x) * 4;
    if (e0 >= N_EDGES) return;
    int s[4], d[4], t[4], c[4];
#pragma unroll
    for (int q = 0; q < 4; q++) {
        s[q] = src[e0 + q]; d[q] = dst[e0 + q]; t[q] = etype[e0 + q];
    }
#pragma unroll
    for (int q = 0; q < 4; q++) c[q] = g_cnt[t[q] * N_NODES + d[q]];
#pragma unroll
    for (int q = 0; q < 4; q++) {
        int b = (s[q] >> 7) * R_REL + t[q];
        int pos = atomicAdd(&g_bcur[b], 1);
        uint2 p;
        p.x = (uint32_t)d[q] | ((uint32_t)(s[q] & 127) << 16);
        p.y = __float_as_uint(1.0f / (float)(c[q] > 0 ? c[q] : 1));
        g_epack[pos] = p;
    }
}

// (4) fused prep, vectorized. Ranges in this order (vec4 units for 0-2):
//   [0, 1.6M)        A1 split (x -> g_A)
//   [1.6M, 3.2M)     h1 bias fill
//   [3.2M, 4.0M)     h2 bias fill
//   then W1 scalar (147456), W2 scalar (81920)
#define PV_A1 1600000LL
#define PV_H1 1600000LL
#define PV_H2 800000LL
#define PS_W1 147456LL
#define PS_W2 81920LL
__global__ void prep_kernel(const float* __restrict__ x,
                            const float* __restrict__ W1, const float* __restrict__ root1,
                            const float* __restrict__ b1,
                            const float* __restrict__ W2, const float* __restrict__ root2,
                            const float* __restrict__ b2) {
    long long i = (long long)blockIdx.x * blockDim.x + threadIdx.x;
    if (i < PV_A1) {
        int n = (int)(i >> 5), j = (int)(i & 31) * 4;
        float4 v = *(const float4*)(x + (long long)n * 128 + j);
        BF4 hi, lo;
        float vv[4] = {v.x, v.y, v.z, v.w};
#pragma unroll
        for (int q = 0; q < 4; q++) {
            __nv_bfloat16 h = __float2bfloat16(vv[q]);
            hi.b[q] = h;
            lo.b[q] = __float2bfloat16(vv[q] - __bfloat162float(h));
        }
        __nv_bfloat16* row = g_A + (long long)n * KTOT;
        *(uint2*)(row + j)       = hi.u;
        *(uint2*)(row + 128 + j) = lo.u;
        *(uint2*)(row + 256 + j) = hi.u;
        return;
    }
    i -= PV_A1;
    if (i < PV_H1) {
        int j = (int)(i & 31) * 4;
        float4 bv = *(const float4*)(b1 + j);
        *(float4*)(g_h1 + i * 4) = bv;
        return;
    }
    i -= PV_H1;
    if (i < PV_H2) {
        int j = (int)(i & 15) * 4;
        float4 bv = *(const float4*)(b2 + j);
        *(float4*)(g_h2 + i * 4) = bv;
        return;
    }
    i -= PV_H2;
    if (i < PS_W1) {
        int n = (int)(i >> 7), k = (int)(i & 127);
        float v;
        if (n < R_REL * 128) {
            int r = n >> 7, o = n & 127;
            v = W1[((long long)r * 128 + k) * 128 + o];
        } else {
            v = root1[k * 128 + (n - R_REL * 128)];
        }
        __nv_bfloat16 h = __float2bfloat16(v);
        __nv_bfloat16 l = __float2bfloat16(v - __bfloat162float(h));
        __nv_bfloat16* row = g_B1 + (long long)n * KTOT;
        row[k] = h; row[128 + k] = h; row[256 + k] = l;
        return;
    }
    i -= PS_W1;
    if (i < PS_W2) {
        int n = (int)(i >> 7), k = (int)(i & 127);
        float v = 0.f;
        if (n < R_REL * 64) {
            int r = n >> 6, o = n & 63;
            v = W2[((long long)r * 128 + k) * 64 + o];
        } else if (n < 576) {
            v = root2[k * 64 + (n - R_REL * 64)];
        }
        __nv_bfloat16 h = __float2bfloat16(v);
        __nv_bfloat16 l = __float2bfloat16(v - __bfloat162float(h));
        __nv_bfloat16* row = g_B2 + (long long)n * KTOT;
        row[k] = h; row[128 + k] = h; row[256 + k] = l;
    }
}

// (6) A-split for layer 2 (relu), vectorized
__global__ void convert_a2_kernel(const float* __restrict__ H) {
    long long i = (long long)blockIdx.x * blockDim.x + threadIdx.x;
    if (i >= PV_A1) return;
    int n = (int)(i >> 5), j = (int)(i & 31) * 4;
    float4 v = *(const float4*)(H + (long long)n * 128 + j);
    BF4 hi, lo;
    float vv[4] = {fmaxf(v.x, 0.f), fmaxf(v.y, 0.f), fmaxf(v.z, 0.f), fmaxf(v.w, 0.f)};
#pragma unroll
    for (int q = 0; q < 4; q++) {
        __nv_bfloat16 h = __float2bfloat16(vv[q]);
        hi.b[q] = h;
        lo.b[q] = __float2bfloat16(vv[q] - __bfloat162float(h));
    }
    __nv_bfloat16* row = g_A + (long long)n * KTOT;
    *(uint2*)(row + j)       = hi.u;
    *(uint2*)(row + 128 + j) = lo.u;
    *(uint2*)(row + 256 + j) = hi.u;
}

// ---------------------------------------------------------------------------
// Fused GEMM + scatter. FH = 128 (layer1) or 64 (layer2).
template <int FH>
__global__ __launch_bounds__(256)
void gemm_fused_kernel(const __nv_bfloat16* __restrict__ A,
                       const __nv_bfloat16* __restrict__ B,
                       float* __restrict__ H, int M) {
    extern __shared__ __align__(1024) char dsm[];
    const uint32_t sA0 = smem_u32(dsm);
    const uint32_t sB0 = sA0 + 3 * BM * BK * 2;

    int tid = threadIdx.x;
    int lane = tid & 31;
    int wid = tid >> 5;
    int warp_m = wid >> 1;
    int warp_n = wid & 1;
    int bm = blockIdx.y * BM;
    int bn = blockIdx.x * BN;

    int lrow = tid >> 1;
    int lch0 = (tid & 1) * 4;
    int arow_g = bm + lrow;
    int a_ok = (arow_g < M) ? 16 : 0;
    if (arow_g >= M) arow_g = M - 1;
    const char* Ag = (const char*)(A + (long long)arow_g * KTOT) + lch0 * 16;
    const char* Bg = (const char*)(B + (long long)(bn + lrow) * KTOT) + lch0 * 16;
    uint32_t swz[4];
#pragma unroll
    for (int q = 0; q < 4; q++) {
        int ch = lch0 + q;
        swz[q] = (uint32_t)lrow * 128u + (uint32_t)((ch ^ (lrow & 7)) * 16);
    }

    float acc[2][8][4];
#pragma unroll
    for (int i = 0; i < 2; i++)
#pragma unroll
        for (int j = 0; j < 8; j++)
#pragma unroll
            for (int q = 0; q < 4; q++) acc[i][j][q] = 0.f;

    const int NKT = KTOT / BK;   // 6

#pragma unroll
    for (int st = 0; st < 2; st++) {
        uint32_t da = sA0 + st * (BM * BK * 2);
        uint32_t db = sB0 + st * (BN * BK * 2);
        const char* ag = Ag + (long long)st * BK * 2;
        const char* bg = Bg + (long long)st * BK * 2;
#pragma unroll
        for (int q = 0; q < 4; q++) {
            cp16(da + swz[q], ag + q * 16, a_ok);
            cp16(db + swz[q], bg + q * 16, 16);
        }
        asm volatile("cp.async.commit_group;" ::: "memory");
    }

    for (int kt = 0; kt < NKT; kt++) {
        if (kt + 2 < NKT) {
            asm volatile("cp.async.wait_group 1;" ::: "memory");
        } else {
            asm volatile("cp.async.wait_group 0;" ::: "memory");
        }
        __syncthreads();
        if (kt + 2 < NKT) {
            int slot = (kt + 2) % 3;
            uint32_t da = sA0 + slot * (BM * BK * 2);
            uint32_t db = sB0 + slot * (BN * BK * 2);
            const char* ag = Ag + (long long)(kt + 2) * BK * 2;
            const char* bg = Bg + (long long)(kt + 2) * BK * 2;
#pragma unroll
            for (int q = 0; q < 4; q++) {
                cp16(da + swz[q], ag + q * 16, a_ok);
                cp16(db + swz[q], bg + q * 16, 16);
            }
            asm volatile("cp.async.commit_group;" ::: "memory");
        }

        int buf = kt % 3;
        uint32_t abuf = sA0 + buf * (BM * BK * 2);
        uint32_t bbuf = sB0 + buf * (BN * BK * 2);

#pragma unroll
        for (int ks = 0; ks < 4; ks++) {
            uint32_t af[2][4];
#pragma unroll
            for (int mf = 0; mf < 2; mf++) {
                int row = warp_m * 32 + mf * 16 + (lane & 15);
                int ch = ks * 2 + (lane >> 4);
                uint32_t addr = abuf + (uint32_t)row * 128u + (uint32_t)((ch ^ (row & 7)) * 16);
                asm volatile("ldmatrix.sync.aligned.m8n8.x4.shared.b16 {%0,%1,%2,%3}, [%4];"
                             : "=r"(af[mf][0]), "=r"(af[mf][1]), "=r"(af[mf][2]), "=r"(af[mf][3])
                             : "r"(addr));
            }
            uint32_t bfr[8][2];
#pragma unroll
            for (int nb = 0; nb < 4; nb++) {
                int n = warp_n * 64 + nb * 16 + ((lane >> 4) * 8) + (lane & 7);
                int ch = ks * 2 + ((lane >> 3) & 1);
                uint32_t addr = bbuf + (uint32_t)n * 128u + (uint32_t)((ch ^ (n & 7)) * 16);
                uint32_t r0, r1, r2, r3;
                asm volatile("ldmatrix.sync.aligned.m8n8.x4.shared.b16 {%0,%1,%2,%3}, [%4];"
                             : "=r"(r0), "=r"(r1), "=r"(r2), "=r"(r3) : "r"(addr));
                bfr[nb * 2][0] = r0;     bfr[nb * 2][1] = r1;
                bfr[nb * 2 + 1][0] = r2; bfr[nb * 2 + 1][1] = r3;
            }
#pragma unroll
            for (int mf = 0; mf < 2; mf++)
#pragma unroll
                for (int nf = 0; nf < 8; nf++) {
                    asm volatile(
                        "mma.sync.aligned.m16n8k16.row.col.f32.bf16.bf16.f32 "
                        "{%0,%1,%2,%3}, {%4,%5,%6,%7}, {%8,%9}, {%0,%1,%2,%3};"
                        : "+f"(acc[mf][nf][0]), "+f"(acc[mf][nf][1]),
                          "+f"(acc[mf][nf][2]), "+f"(acc[mf][nf][3])
                        : "r"(af[mf][0]), "r"(af[mf][1]), "r"(af[mf][2]), "r"(af[mf][3]),
                          "r"(bfr[nf][0]), "r"(bfr[nf][1]));
                }
        }
        __syncthreads();
    }

    int g = lane >> 2, tg = lane & 3;
    const bool is_root = (FH == 128) ? (blockIdx.x == 8) : (blockIdx.x == 4);

    if (is_root) {
        if (FH == 64 && warp_n == 1) return;
#pragma unroll
        for (int mf = 0; mf < 2; mf++) {
            int row0 = bm + warp_m * 32 + mf * 16 + g;
#pragma unroll
            for (int nf = 0; nf < 8; nf++) {
                int colh = ((FH == 128) ? warp_n * 64 : 0) + nf * 8 + tg * 2;
                if (row0 < M)
                    asm volatile("red.global.add.v2.f32 [%0], {%1, %2};"
                                 :: "l"(H + (long long)row0 * FH + colh),
                                    "f"(acc[mf][nf][0]), "f"(acc[mf][nf][1]) : "memory");
                if (row0 + 8 < M)
                    asm volatile("red.global.add.v2.f32 [%0], {%1, %2};"
                                 :: "l"(H + (long long)(row0 + 8) * FH + colh),
                                    "f"(acc[mf][nf][2]), "f"(acc[mf][nf][3]) : "memory");
            }
        }
        return;
    }

    // stage result tile into smem (128x128 f32)
    float* stg = (float*)dsm;
#pragma unroll
    for (int mf = 0; mf < 2; mf++) {
        int r0 = warp_m * 32 + mf * 16 + g;
#pragma unroll
        for (int nf = 0; nf < 8; nf++) {
            int c = warp_n * 64 + nf * 8 + tg * 2;
            *(float2*)(stg + r0 * 128 + c)       = make_float2(acc[mf][nf][0], acc[mf][nf][1]);
            *(float2*)(stg + (r0 + 8) * 128 + c) = make_float2(acc[mf][nf][2], acc[mf][nf][3]);
        }
    }
    __syncthreads();

    // scatter bucket edges
    if (FH == 128) {
        int b = blockIdx.y * R_REL + blockIdx.x;
        int s0 = g_boff[b], cnt = g_bkt[b];
        for (int i = wid; i < cnt; i += 8) {
            uint2 p = g_epack[s0 + i];
            float w = __uint_as_float(p.y);
            int sl = (int)(p.x >> 16);
            int d = (int)(p.x & 0xFFFFu);
            float4 v = *(const float4*)(stg + sl * 128 + lane * 4);
            v.x *= w; v.y *= w; v.z *= w; v.w *= w;
            asm volatile("red.global.add.v4.f32 [%0], {%1, %2, %3, %4};"
                         :: "l"(H + (long long)d * 128 + lane * 4),
                            "f"(v.x), "f"(v.y), "f"(v.z), "f"(v.w) : "memory");
        }
    } else {
        int half = wid >> 2;
        int b = blockIdx.y * R_REL + blockIdx.x * 2 + half;
        int s0 = g_boff[b], cnt = g_bkt[b];
        for (int i = (wid & 3); i < cnt; i += 4) {
            uint2 p = g_epack[s0 + i];
            float w = __uint_as_float(p.y);
            int sl = (int)(p.x >> 16);
            int d = (int)(p.x & 0xFFFFu);
            float2 v = *(const float2*)(stg + sl * 128 + half * 64 + lane * 2);
            v.x *= w; v.y *= w;
            asm volatile("red.global.add.v2.f32 [%0], {%1, %2};"
                         :: "l"(H + (long long)d * 64 + lane * 2),
                            "f"(v.x), "f"(v.y) : "memory");
        }
    }
}

// ---------------------------------------------------------------------------
__global__ __launch_bounds__(256)
void classifier_kernel(const float* __restrict__ Wc, const float* __restrict__ bc,
                       float* __restrict__ out) {
    int n = (int)(((long long)blockIdx.x * blockDim.x + threadIdx.x) >> 5);
    int lane = threadIdx.x & 31;
    if (n >= N_NODES) return;
    float a0 = 0.f, a1 = 0.f;
#pragma unroll
    for (int o = lane; o < 64; o += 32) {
        float v = fmaxf(g_h2[(long long)n * 64 + o], 0.f);
        a0 += v * Wc[o * 2 + 0];
        a1 += v * Wc[o * 2 + 1];
    }
#pragma unroll
    for (int off = 16; off; off >>= 1) {
        a0 += __shfl_down_sync(0xffffffffu, a0, off);
        a1 += __shfl_down_sync(0xffffffffu, a1, off);
    }
    if (lane == 0) {
        out[n * 2 + 0] = a0 + bc[0];
        out[n * 2 + 1] = a1 + bc[1];
    }
}

// ---------------------------------------------------------------------------
extern "C" void kernel_launch(void* const* d_in, const int* in_sizes, int n_in,
                              void* d_out, int out_size) {
    const float* x     = (const float*)d_in[0];
    const int*   eidx  = (const int*)d_in[1];
    const int*   etype = (const int*)d_in[2];
    const float* W1    = (const float*)d_in[3];
    const float* root1 = (const float*)d_in[4];
    const float* b1    = (const float*)d_in[5];
    const float* W2    = (const float*)d_in[6];
    const float* root2 = (const float*)d_in[7];
    const float* b2    = (const float*)d_in[8];
    const float* Wc    = (const float*)d_in[9];
    const float* bc    = (const float*)d_in[10];
    float* logits = (float*)d_out;

    const int* src = eidx;
    const int* dst = eidx + N_EDGES;

    float* h1p; cudaGetSymbolAddress((void**)&h1p, g_h1);
    float* h2p; cudaGetSymbolAddress((void**)&h2p, g_h2);
    __nv_bfloat16* Ap;  cudaGetSymbolAddress((void**)&Ap, g_A);
    __nv_bfloat16* B1p; cudaGetSymbolAddress((void**)&B1p, g_B1);
    __nv_bfloat16* B2p; cudaGetSymbolAddress((void**)&B2p, g_B2);
    int* cntp; cudaGetSymbolAddress((void**)&cntp, g_cnt);
    int* bktp; cudaGetSymbolAddress((void**)&bktp, g_bkt);

    const int GEMM_SMEM = 3 * 2 * BM * BK * 2;   // 96KB
    static int attr_done = 0;
    if (!attr_done) {
        cudaFuncSetAttribute(gemm_fused_kernel<128>, cudaFuncAttributeMaxDynamicSharedMemorySize, GEMM_SMEM);
        cudaFuncSetAttribute(gemm_fused_kernel<64>,  cudaFuncAttributeMaxDynamicSharedMemorySize, GEMM_SMEM);
        attr_done = 1;
    }

    // zero counters (driver memset, capturable)
    cudaMemsetAsync(cntp, 0, R_REL * N_NODES * sizeof(int));
    cudaMemsetAsync(bktp, 0, NBKT * sizeof(int));
    // histograms (4 edges/thread)
    count_kernel<<<N_EDGES / 1024, 256>>>(src, dst, etype);
    // bucket scan
    scan_kernel<<<1, 1024>>>();
    // bucket-sorted packed edges (4 edges/thread)
    fill_kernel<<<N_EDGES / 1024, 256>>>(src, dst, etype);
    // fused prep (vectorized A-split, bias fills; scalar W-splits)
    {
        long long total = PV_A1 + PV_H1 + PV_H2 + PS_W1 + PS_W2;
        prep_kernel<<<(int)((total + 255) / 256), 256>>>(x, W1, root1, b1, W2, root2, b2);
    }
    // layer-1 fused GEMM+scatter
    {
        dim3 grid(NW1 / BN, (N_NODES + BM - 1) / BM);
        gemm_fused_kernel<128><<<grid, 256, GEMM_SMEM>>>(Ap, B1p, h1p, N_NODES);
    }
    // layer-2 A split (relu, vectorized)
    convert_a2_kernel<<<(int)((PV_A1 + 255) / 256), 256>>>(h1p);
    // layer-2 fused GEMM+scatter
    {
        dim3 grid(NW2 / BN, (N_NODES + BM - 1) / BM);
        gemm_fused_kernel<64><<<grid, 256, GEMM_SMEM>>>(Ap, B2p, h2p, N_NODES);
    }
    // classifier
    classifier_kernel<<<(int)(((long long)N_NODES * 32 + 255) / 256), 256>>>(Wc, bc, logits);
}

// round 6
// speedup vs baseline: 1.1817x; 1.1817x over previous
#include <cuda_runtime.h>
#include <cuda_fp16.h>
#include <cstdint>

// Problem constants
#define N_NODES 50000
#define N_EDGES 640000
#define R_REL   8
#define NW1     1152           // (R+1)*128
#define NW2     640            // (R+1)*64 = 576 padded to 640
#define KTOT    256            // [Ah|Al] fp16 2-term split K
#define MT      391            // ceil(50000/128)
#define NBKT    (MT * R_REL)   // 3128

#define BM 128
#define BN 128
#define BK 64

// ---------------------------------------------------------------------------
// Device scratch
__device__ float  g_h1[(long long)N_NODES * 128];
__device__ float  g_h2[(long long)N_NODES * 64];
__device__ int    g_cntbkt[R_REL * N_NODES + NBKT];  // [0,R*N): cnt, [R*N,+NBKT): bkt
__device__ __half g_A[(long long)N_NODES * KTOT];
__device__ __half g_B1[NW1 * KTOT];
__device__ __half g_B2[NW2 * KTOT];
__device__ int    g_boff[NBKT];
__device__ int    g_bcur[NBKT];
__device__ uint2  g_epack[N_EDGES];   // {dst|(src&127)<<16, f32bits(w)}

#define CNT(i) g_cntbkt[i]
#define BKT(i) g_cntbkt[R_REL * N_NODES + (i)]

__device__ __forceinline__ uint32_t smem_u32(const void* p) {
    uint32_t a;
    asm("{ .reg .u64 t; cvta.to.shared.u64 t, %1; cvt.u32.u64 %0, t; }" : "=r"(a) : "l"(p));
    return a;
}
__device__ __forceinline__ void cp16(uint32_t dst, const void* src, int src_sz) {
    asm volatile("cp.async.cg.shared.global [%0], [%1], 16, %2;"
                 :: "r"(dst), "l"(src), "r"(src_sz));
}

union HF4 { __half h[4]; uint2 u; };

// ---------------------------------------------------------------------------
// (1) histogram, 4 edges/thread
__global__ void count_kernel(const int* __restrict__ src, const int* __restrict__ dst,
                             const int* __restrict__ etype) {
    int e0 = (blockIdx.x * blockDim.x + threadIdx.x) * 4;
    if (e0 >= N_EDGES) return;
    int t[4], d[4], s[4];
#pragma unroll
    for (int q = 0; q < 4; q++) {
        t[q] = etype[e0 + q]; d[q] = dst[e0 + q]; s[q] = src[e0 + q];
    }
#pragma unroll
    for (int q = 0; q < 4; q++) {
        atomicAdd(&CNT(t[q] * N_NODES + d[q]), 1);
        atomicAdd(&BKT((s[q] >> 7) * R_REL + t[q]), 1);
    }
}

// (2) exclusive scan over NBKT buckets
__global__ void scan_kernel() {
    __shared__ int tsum[1024];
    int tid = threadIdx.x;
    int base = tid * 4;
    int v[4]; int s = 0;
#pragma unroll
    for (int q = 0; q < 4; q++) {
        v[q] = (base + q < NBKT) ? BKT(base + q) : 0;
        s += v[q];
    }
    tsum[tid] = s;
    __syncthreads();
    for (int off = 1; off < 1024; off <<= 1) {
        int t = (tid >= off) ? tsum[tid - off] : 0;
        __syncthreads();
        tsum[tid] += t;
        __syncthreads();
    }
    int ex = tsum[tid] - s;
#pragma unroll
    for (int q = 0; q < 4; q++) {
        if (base + q < NBKT) { g_boff[base + q] = ex; g_bcur[base + q] = ex; }
        ex += v[q];
    }
}

// (3) bucket-sorted packed edges, 4 edges/thread
__global__ void fill_kernel(const int* __restrict__ src, const int* __restrict__ dst,
                            const int* __restrict__ etype) {
    int e0 = (blockIdx.x * blockDim.x + threadIdx.x) * 4;
    if (e0 >= N_EDGES) return;
    int s[4], d[4], t[4], c[4];
#pragma unroll
    for (int q = 0; q < 4; q++) {
        s[q] = src[e0 + q]; d[q] = dst[e0 + q]; t[q] = etype[e0 + q];
    }
#pragma unroll
    for (int q = 0; q < 4; q++) c[q] = CNT(t[q] * N_NODES + d[q]);
#pragma unroll
    for (int q = 0; q < 4; q++) {
        int b = (s[q] >> 7) * R_REL + t[q];
        int pos = atomicAdd(&g_bcur[b], 1);
        uint2 p;
        p.x = (uint32_t)d[q] | ((uint32_t)(s[q] & 127) << 16);
        p.y = __float_as_uint(1.0f / (float)(c[q] > 0 ? c[q] : 1));
        g_epack[pos] = p;
    }
}

// (4) fused prep: A1 fp16 split (vec4), h bias fills (vec4), W splits (scalar)
#define PV_A1 1600000LL
#define PV_H1 1600000LL
#define PV_H2 800000LL
#define PS_W1 147456LL
#define PS_W2 81920LL
__global__ void prep_kernel(const float* __restrict__ x,
                            const float* __restrict__ W1, const float* __restrict__ root1,
                            const float* __restrict__ b1,
                            const float* __restrict__ W2, const float* __restrict__ root2,
                            const float* __restrict__ b2) {
    long long i = (long long)blockIdx.x * blockDim.x + threadIdx.x;
    if (i < PV_A1) {
        int n = (int)(i >> 5), j = (int)(i & 31) * 4;
        float4 v = *(const float4*)(x + (long long)n * 128 + j);
        HF4 hi, lo;
        float vv[4] = {v.x, v.y, v.z, v.w};
#pragma unroll
        for (int q = 0; q < 4; q++) {
            __half h = __float2half(vv[q]);
            hi.h[q] = h;
            lo.h[q] = __float2half(vv[q] - __half2float(h));
        }
        __half* row = g_A + (long long)n * KTOT;
        *(uint2*)(row + j)       = hi.u;
        *(uint2*)(row + 128 + j) = lo.u;
        return;
    }
    i -= PV_A1;
    if (i < PV_H1) {
        int j = (int)(i & 31) * 4;
        float4 bv = *(const float4*)(b1 + j);
        *(float4*)(g_h1 + i * 4) = bv;
        return;
    }
    i -= PV_H1;
    if (i < PV_H2) {
        int j = (int)(i & 15) * 4;
        float4 bv = *(const float4*)(b2 + j);
        *(float4*)(g_h2 + i * 4) = bv;
        return;
    }
    i -= PV_H2;
    if (i < PS_W1) {
        int n = (int)(i >> 7), k = (int)(i & 127);
        float v;
        if (n < R_REL * 128) {
            int r = n >> 7, o = n & 127;
            v = W1[((long long)r * 128 + k) * 128 + o];
        } else {
            v = root1[k * 128 + (n - R_REL * 128)];
        }
        __half h = __float2half(v);
        __half* row = g_B1 + (long long)n * KTOT;
        row[k] = h; row[128 + k] = h;
        return;
    }
    i -= PS_W1;
    if (i < PS_W2) {
        int n = (int)(i >> 7), k = (int)(i & 127);
        float v = 0.f;
        if (n < R_REL * 64) {
            int r = n >> 6, o = n & 63;
            v = W2[((long long)r * 128 + k) * 64 + o];
        } else if (n < 576) {
            v = root2[k * 64 + (n - R_REL * 64)];
        }
        __half h = __float2half(v);
        __half* row = g_B2 + (long long)n * KTOT;
        row[k] = h; row[128 + k] = h;
    }
}

// (6) A-split for layer 2 (relu), vectorized
__global__ void convert_a2_kernel(const float* __restrict__ H) {
    long long i = (long long)blockIdx.x * blockDim.x + threadIdx.x;
    if (i >= PV_A1) return;
    int n = (int)(i >> 5), j = (int)(i & 31) * 4;
    float4 v = *(const float4*)(H + (long long)n * 128 + j);
    HF4 hi, lo;
    float vv[4] = {fmaxf(v.x, 0.f), fmaxf(v.y, 0.f), fmaxf(v.z, 0.f), fmaxf(v.w, 0.f)};
#pragma unroll
    for (int q = 0; q < 4; q++) {
        __half h = __float2half(vv[q]);
        hi.h[q] = h;
        lo.h[q] = __float2half(vv[q] - __half2float(h));
    }
    __half* row = g_A + (long long)n * KTOT;
    *(uint2*)(row + j)       = hi.u;
    *(uint2*)(row + 128 + j) = lo.u;
}

// ---------------------------------------------------------------------------
// Fused GEMM + scatter. FH = 128 (layer1) or 64 (layer2). fp16 inputs, f32 acc.
template <int FH>
__global__ __launch_bounds__(256)
void gemm_fused_kernel(const __half* __restrict__ A,
                       const __half* __restrict__ B,
                       float* __restrict__ H, int M) {
    extern __shared__ __align__(1024) char dsm[];
    const uint32_t sA0 = smem_u32(dsm);
    const uint32_t sB0 = sA0 + 3 * BM * BK * 2;

    int tid = threadIdx.x;
    int lane = tid & 31;
    int wid = tid >> 5;
    int warp_m = wid >> 1;
    int warp_n = wid & 1;
    int bm = blockIdx.y * BM;
    int bn = blockIdx.x * BN;

    int lrow = tid >> 1;
    int lch0 = (tid & 1) * 4;
    int arow_g = bm + lrow;
    int a_ok = (arow_g < M) ? 16 : 0;
    if (arow_g >= M) arow_g = M - 1;
    const char* Ag = (const char*)(A + (long long)arow_g * KTOT) + lch0 * 16;
    const char* Bg = (const char*)(B + (long long)(bn + lrow) * KTOT) + lch0 * 16;
    uint32_t swz[4];
#pragma unroll
    for (int q = 0; q < 4; q++) {
        int ch = lch0 + q;
        swz[q] = (uint32_t)lrow * 128u + (uint32_t)((ch ^ (lrow & 7)) * 16);
    }

    float acc[2][8][4];
#pragma unroll
    for (int i = 0; i < 2; i++)
#pragma unroll
        for (int j = 0; j < 8; j++)
#pragma unroll
            for (int q = 0; q < 4; q++) acc[i][j][q] = 0.f;

    const int NKT = KTOT / BK;   // 4

#pragma unroll
    for (int st = 0; st < 2; st++) {
        uint32_t da = sA0 + st * (BM * BK * 2);
        uint32_t db = sB0 + st * (BN * BK * 2);
        const char* ag = Ag + (long long)st * BK * 2;
        const char* bg = Bg + (long long)st * BK * 2;
#pragma unroll
        for (int q = 0; q < 4; q++) {
            cp16(da + swz[q], ag + q * 16, a_ok);
            cp16(db + swz[q], bg + q * 16, 16);
        }
        asm volatile("cp.async.commit_group;" ::: "memory");
    }

    for (int kt = 0; kt < NKT; kt++) {
        if (kt + 2 < NKT) {
            asm volatile("cp.async.wait_group 1;" ::: "memory");
        } else {
            asm volatile("cp.async.wait_group 0;" ::: "memory");
        }
        __syncthreads();
        if (kt + 2 < NKT) {
            int slot = (kt + 2) % 3;
            uint32_t da = sA0 + slot * (BM * BK * 2);
            uint32_t db = sB0 + slot * (BN * BK * 2);
            const char* ag = Ag + (long long)(kt + 2) * BK * 2;
            const char* bg = Bg + (long long)(kt + 2) * BK * 2;
#pragma unroll
            for (int q = 0; q < 4; q++) {
                cp16(da + swz[q], ag + q * 16, a_ok);
                cp16(db + swz[q], bg + q * 16, 16);
            }
            asm volatile("cp.async.commit_group;" ::: "memory");
        }

        int buf = kt % 3;
        uint32_t abuf = sA0 + buf * (BM * BK * 2);
        uint32_t bbuf = sB0 + buf * (BN * BK * 2);

#pragma unroll
        for (int ks = 0; ks < 4; ks++) {
            uint32_t af[2][4];
#pragma unroll
            for (int mf = 0; mf < 2; mf++) {
                int row = warp_m * 32 + mf * 16 + (lane & 15);
                int ch = ks * 2 + (lane >> 4);
                uint32_t addr = abuf + (uint32_t)row * 128u + (uint32_t)((ch ^ (row & 7)) * 16);
                asm volatile("ldmatrix.sync.aligned.m8n8.x4.shared.b16 {%0,%1,%2,%3}, [%4];"
                             : "=r"(af[mf][0]), "=r"(af[mf][1]), "=r"(af[mf][2]), "=r"(af[mf][3])
                             : "r"(addr));
            }
            uint32_t bfr[8][2];
#pragma unroll
            for (int nb = 0; nb < 4; nb++) {
                int n = warp_n * 64 + nb * 16 + ((lane >> 4) * 8) + (lane & 7);
                int ch = ks * 2 + ((lane >> 3) & 1);
                uint32_t addr = bbuf + (uint32_t)n * 128u + (uint32_t)((ch ^ (n & 7)) * 16);
                uint32_t r0, r1, r2, r3;
                asm volatile("ldmatrix.sync.aligned.m8n8.x4.shared.b16 {%0,%1,%2,%3}, [%4];"
                             : "=r"(r0), "=r"(r1), "=r"(r2), "=r"(r3) : "r"(addr));
                bfr[nb * 2][0] = r0;     bfr[nb * 2][1] = r1;
                bfr[nb * 2 + 1][0] = r2; bfr[nb * 2 + 1][1] = r3;
            }
#pragma unroll
            for (int mf = 0; mf < 2; mf++)
#pragma unroll
                for (int nf = 0; nf < 8; nf++) {
                    asm volatile(
                        "mma.sync.aligned.m16n8k16.row.col.f32.f16.f16.f32 "
                        "{%0,%1,%2,%3}, {%4,%5,%6,%7}, {%8,%9}, {%0,%1,%2,%3};"
                        : "+f"(acc[mf][nf][0]), "+f"(acc[mf][nf][1]),
                          "+f"(acc[mf][nf][2]), "+f"(acc[mf][nf][3])
                        : "r"(af[mf][0]), "r"(af[mf][1]), "r"(af[mf][2]), "r"(af[mf][3]),
                          "r"(bfr[nf][0]), "r"(bfr[nf][1]));
                }
        }
        __syncthreads();
    }

    int g = lane >> 2, tg = lane & 3;
    const bool is_root = (FH == 128) ? (blockIdx.x == 8) : (blockIdx.x == 4);

    if (is_root) {
        if (FH == 64 && warp_n == 1) return;
#pragma unroll
        for (int mf = 0; mf < 2; mf++) {
            int row0 = bm + warp_m * 32 + mf * 16 + g;
#pragma unroll
            for (int nf = 0; nf < 8; nf++) {
                int colh = ((FH == 128) ? warp_n * 64 : 0) + nf * 8 + tg * 2;
                if (row0 < M)
                    asm volatile("red.global.add.v2.f32 [%0], {%1, %2};"
                                 :: "l"(H + (long long)row0 * FH + colh),
                                    "f"(acc[mf][nf][0]), "f"(acc[mf][nf][1]) : "memory");
                if (row0 + 8 < M)
                    asm volatile("red.global.add.v2.f32 [%0], {%1, %2};"
                                 :: "l"(H + (long long)(row0 + 8) * FH + colh),
                                    "f"(acc[mf][nf][2]), "f"(acc[mf][nf][3]) : "memory");
            }
        }
        return;
    }

    // stage result tile into smem
    float* stg = (float*)dsm;
#pragma unroll
    for (int mf = 0; mf < 2; mf++) {
        int r0 = warp_m * 32 + mf * 16 + g;
#pragma unroll
        for (int nf = 0; nf < 8; nf++) {
            int c = warp_n * 64 + nf * 8 + tg * 2;
            *(float2*)(stg + r0 * 128 + c)       = make_float2(acc[mf][nf][0], acc[mf][nf][1]);
            *(float2*)(stg + (r0 + 8) * 128 + c) = make_float2(acc[mf][nf][2], acc[mf][nf][3]);
        }
    }
    __syncthreads();

    // scatter bucket edges
    if (FH == 128) {
        int b = blockIdx.y * R_REL + blockIdx.x;
        int s0 = g_boff[b], cnt = BKT(b);
        for (int i = wid; i < cnt; i += 8) {
            uint2 p = g_epack[s0 + i];
            float w = __uint_as_float(p.y);
            int sl = (int)(p.x >> 16);
            int d = (int)(p.x & 0xFFFFu);
            float4 v = *(const float4*)(stg + sl * 128 + lane * 4);
            v.x *= w; v.y *= w; v.z *= w; v.w *= w;
            asm volatile("red.global.add.v4.f32 [%0], {%1, %2, %3, %4};"
                         :: "l"(H + (long long)d * 128 + lane * 4),
                            "f"(v.x), "f"(v.y), "f"(v.z), "f"(v.w) : "memory");
        }
    } else {
        int half = wid >> 2;
        int b = blockIdx.y * R_REL + blockIdx.x * 2 + half;
        int s0 = g_boff[b], cnt = BKT(b);
        for (int i = (wid & 3); i < cnt; i += 4) {
            uint2 p = g_epack[s0 + i];
            float w = __uint_as_float(p.y);
            int sl = (int)(p.x >> 16);
            int d = (int)(p.x & 0xFFFFu);
            float2 v = *(const float2*)(stg + sl * 128 + half * 64 + lane * 2);
            v.x *= w; v.y *= w;
            asm volatile("red.global.add.v2.f32 [%0], {%1, %2};"
                         :: "l"(H + (long long)d * 64 + lane * 2),
                            "f"(v.x), "f"(v.y) : "memory");
        }
    }
}

// ---------------------------------------------------------------------------
__global__ __launch_bounds__(256)
void classifier_kernel(const float* __restrict__ Wc, const float* __restrict__ bc,
                       float* __restrict__ out) {
    int n = (int)(((long long)blockIdx.x * blockDim.x + threadIdx.x) >> 5);
    int lane = threadIdx.x & 31;
    if (n >= N_NODES) return;
    float a0 = 0.f, a1 = 0.f;
#pragma unroll
    for (int o = lane; o < 64; o += 32) {
        float v = fmaxf(g_h2[(long long)n * 64 + o], 0.f);
        a0 += v * Wc[o * 2 + 0];
        a1 += v * Wc[o * 2 + 1];
    }
#pragma unroll
    for (int off = 16; off; off >>= 1) {
        a0 += __shfl_down_sync(0xffffffffu, a0, off);
        a1 += __shfl_down_sync(0xffffffffu, a1, off);
    }
    if (lane == 0) {
        out[n * 2 + 0] = a0 + bc[0];
        out[n * 2 + 1] = a1 + bc[1];
    }
}

// ---------------------------------------------------------------------------
extern "C" void kernel_launch(void* const* d_in, const int* in_sizes, int n_in,
                              void* d_out, int out_size) {
    const float* x     = (const float*)d_in[0];
    const int*   eidx  = (const int*)d_in[1];
    const int*   etype = (const int*)d_in[2];
    const float* W1    = (const float*)d_in[3];
    const float* root1 = (const float*)d_in[4];
    const float* b1    = (const float*)d_in[5];
    const float* W2    = (const float*)d_in[6];
    const float* root2 = (const float*)d_in[7];
    const float* b2    = (const float*)d_in[8];
    const float* Wc    = (const float*)d_in[9];
    const float* bc    = (const float*)d_in[10];
    float* logits = (float*)d_out;

    const int* src = eidx;
    const int* dst = eidx + N_EDGES;

    float* h1p; cudaGetSymbolAddress((void**)&h1p, g_h1);
    float* h2p; cudaGetSymbolAddress((void**)&h2p, g_h2);
    __half* Ap;  cudaGetSymbolAddress((void**)&Ap, g_A);
    __half* B1p; cudaGetSymbolAddress((void**)&B1p, g_B1);
    __half* B2p; cudaGetSymbolAddress((void**)&B2p, g_B2);
    int* cbp; cudaGetSymbolAddress((void**)&cbp, g_cntbkt);

    const int GEMM_SMEM = 3 * 2 * BM * BK * 2;   // 96KB
    static int attr_done = 0;
    if (!attr_done) {
        cudaFuncSetAttribute(gemm_fused_kernel<128>, cudaFuncAttributeMaxDynamicSharedMemorySize, GEMM_SMEM);
        cudaFuncSetAttribute(gemm_fused_kernel<64>,  cudaFuncAttributeMaxDynamicSharedMemorySize, GEMM_SMEM);
        attr_done = 1;
    }

    // [0] zero counters (one memset over merged buffer)
    cudaMemsetAsync(cbp, 0, (R_REL * N_NODES + NBKT) * sizeof(int));
    // [1] histograms
    count_kernel<<<N_EDGES / 1024, 256>>>(src, dst, etype);
    // [2] bucket scan
    scan_kernel<<<1, 1024>>>();
    // [3] bucket-sorted packed edges
    fill_kernel<<<N_EDGES / 1024, 256>>>(src, dst, etype);
    // [4] fused prep
    {
        long long total = PV_A1 + PV_H1 + PV_H2 + PS_W1 + PS_W2;
        prep_kernel<<<(int)((total + 255) / 256), 256>>>(x, W1, root1, b1, W2, root2, b2);
    }
    // [5] layer-1 fused GEMM+scatter (profiled launch)
    {
        dim3 grid(NW1 / BN, (N_NODES + BM - 1) / BM);
        gemm_fused_kernel<128><<<grid, 256, GEMM_SMEM>>>(Ap, B1p, h1p, N_NODES);
    }
    // [6] layer-2 A split (relu)
    convert_a2_kernel<<<(int)((PV_A1 + 255) / 256), 256>>>(h1p);
    // [7] layer-2 fused GEMM+scatter
    {
        dim3 grid(NW2 / BN, (N_NODES + BM - 1) / BM);
        gemm_fused_kernel<64><<<grid, 256, GEMM_SMEM>>>(Ap, B2p, h2p, N_NODES);
    }
    // [8] classifier
    classifier_kernel<<<(int)(((long long)N_NODES * 32 + 255) / 256), 256>>>(Wc, bc, logits);
}

// round 7
// speedup vs baseline: 1.5520x; 1.3134x over previous
#include <cuda_runtime.h>
#include <cuda_fp16.h>
#include <cstdint>

// Problem constants
#define N_NODES 50000
#define N_EDGES 640000
#define R_REL   8
#define NSEG    (N_NODES * R_REL)   // 400000 segments, key = dst*8+rel
#define NW1     1152                // (R+1)*128
#define NW2     640                 // (R+1)*64 = 576 padded to 640
#define KTOT    256                 // [Ah|Al] fp16 2-term split K

#define BM 128
#define BN 128
#define BK 64

// scan config
#define SCH  512                    // chunk
#define NCH  ((NSEG + SCH - 1) / SCH)  // 782

// ---------------------------------------------------------------------------
// Device scratch
__device__ float  g_Y[(long long)N_NODES * NW1];   // GEMM out (layer-reused)
__device__ int    g_segcnt[NSEG];
__device__ int    g_bsum[NCH];
__device__ int    g_bsum_ex[NCH];
__device__ int    g_boff[NSEG + 1];
__device__ int    g_bcur[NSEG];
__device__ int    g_esrc[N_EDGES];                 // src per edge, segment-sorted
__device__ __half g_A[(long long)N_NODES * KTOT];
__device__ __half g_B1[NW1 * KTOT];
__device__ __half g_B2[NW2 * KTOT];

__device__ __forceinline__ uint32_t smem_u32(const void* p) {
    uint32_t a;
    asm("{ .reg .u64 t; cvta.to.shared.u64 t, %1; cvt.u32.u64 %0, t; }" : "=r"(a) : "l"(p));
    return a;
}
__device__ __forceinline__ void cp16(uint32_t dst, const void* src, int src_sz) {
    asm volatile("cp.async.cg.shared.global [%0], [%1], 16, %2;"
                 :: "r"(dst), "l"(src), "r"(src_sz));
}
union HF4 { __half h[4]; uint2 u; };

// ---------------------------------------------------------------------------
// (1) per-segment histogram, 4 edges/thread
__global__ void count_kernel(const int* __restrict__ src, const int* __restrict__ dst,
                             const int* __restrict__ etype) {
    int e0 = (blockIdx.x * blockDim.x + threadIdx.x) * 4;
    if (e0 >= N_EDGES) return;
    int t[4], d[4];
#pragma unroll
    for (int q = 0; q < 4; q++) { t[q] = etype[e0 + q]; d[q] = dst[e0 + q]; }
#pragma unroll
    for (int q = 0; q < 4; q++) atomicAdd(&g_segcnt[d[q] * R_REL + t[q]], 1);
}

// (2a) per-chunk reduce
__global__ void scan_reduce_kernel() {
    __shared__ int sh[SCH];
    int i = blockIdx.x * SCH + threadIdx.x;
    sh[threadIdx.x] = (i < NSEG) ? g_segcnt[i] : 0;
    __syncthreads();
    for (int off = SCH / 2; off > 0; off >>= 1) {
        if (threadIdx.x < off) sh[threadIdx.x] += sh[threadIdx.x + off];
        __syncthreads();
    }
    if (threadIdx.x == 0) g_bsum[blockIdx.x] = sh[0];
}

// (2b) scan chunk sums (single block, 1024 threads >= NCH)
__global__ void scan_block_kernel() {
    __shared__ int sh[1024];
    int t = threadIdx.x;
    int v = (t < NCH) ? g_bsum[t] : 0;
    sh[t] = v;
    __syncthreads();
    for (int off = 1; off < 1024; off <<= 1) {
        int tv = (t >= off) ? sh[t - off] : 0;
        __syncthreads();
        sh[t] += tv;
        __syncthreads();
    }
    if (t < NCH) g_bsum_ex[t] = sh[t] - v;
    if (t == 1023) g_boff[NSEG] = sh[t];   // total = E
}

// (2c) per-chunk exclusive scan -> boff, bcur
__global__ void scan_final_kernel() {
    __shared__ int sh[SCH];
    int i = blockIdx.x * SCH + threadIdx.x;
    int v = (i < NSEG) ? g_segcnt[i] : 0;
    sh[threadIdx.x] = v;
    __syncthreads();
    for (int off = 1; off < SCH; off <<= 1) {
        int tv = (threadIdx.x >= off) ? sh[threadIdx.x - off] : 0;
        __syncthreads();
        sh[threadIdx.x] += tv;
        __syncthreads();
    }
    if (i < NSEG) {
        int ex = sh[threadIdx.x] - v + g_bsum_ex[blockIdx.x];
        g_boff[i] = ex;
        g_bcur[i] = ex;
    }
}

// (3) segment-sorted edge source array, 4 edges/thread
__global__ void fill_kernel(const int* __restrict__ src, const int* __restrict__ dst,
                            const int* __restrict__ etype) {
    int e0 = (blockIdx.x * blockDim.x + threadIdx.x) * 4;
    if (e0 >= N_EDGES) return;
    int s[4], d[4], t[4];
#pragma unroll
    for (int q = 0; q < 4; q++) {
        s[q] = src[e0 + q]; d[q] = dst[e0 + q]; t[q] = etype[e0 + q];
    }
#pragma unroll
    for (int q = 0; q < 4; q++) {
        int pos = atomicAdd(&g_bcur[d[q] * R_REL + t[q]], 1);
        g_esrc[pos] = s[q];
    }
}

// (4) prep: A1 fp16 split (vec4) + W1/W2 splits (scalar)
#define PV_A1 1600000LL
#define PS_W1 147456LL
#define PS_W2 81920LL
__global__ void prep_kernel(const float* __restrict__ x,
                            const float* __restrict__ W1, const float* __restrict__ root1,
                            const float* __restrict__ W2, const float* __restrict__ root2) {
    long long i = (long long)blockIdx.x * blockDim.x + threadIdx.x;
    if (i < PV_A1) {
        int n = (int)(i >> 5), j = (int)(i & 31) * 4;
        float4 v = *(const float4*)(x + (long long)n * 128 + j);
        HF4 hi, lo;
        float vv[4] = {v.x, v.y, v.z, v.w};
#pragma unroll
        for (int q = 0; q < 4; q++) {
            __half h = __float2half(vv[q]);
            hi.h[q] = h;
            lo.h[q] = __float2half(vv[q] - __half2float(h));
        }
        __half* row = g_A + (long long)n * KTOT;
        *(uint2*)(row + j)       = hi.u;
        *(uint2*)(row + 128 + j) = lo.u;
        return;
    }
    i -= PV_A1;
    if (i < PS_W1) {
        int n = (int)(i >> 7), k = (int)(i & 127);
        float v;
        if (n < R_REL * 128) {
            int r = n >> 7, o = n & 127;
            v = W1[((long long)r * 128 + k) * 128 + o];
        } else {
            v = root1[k * 128 + (n - R_REL * 128)];
        }
        __half h = __float2half(v);
        __half* row = g_B1 + (long long)n * KTOT;
        row[k] = h; row[128 + k] = h;
        return;
    }
    i -= PS_W1;
    if (i < PS_W2) {
        int n = (int)(i >> 7), k = (int)(i & 127);
        float v = 0.f;
        if (n < R_REL * 64) {
            int r = n >> 6, o = n & 63;
            v = W2[((long long)r * 128 + k) * 64 + o];
        } else if (n < 576) {
            v = root2[k * 64 + (n - R_REL * 64)];
        }
        __half h = __float2half(v);
        __half* row = g_B2 + (long long)n * KTOT;
        row[k] = h; row[128 + k] = h;
    }
}

// ---------------------------------------------------------------------------
// Plain fp16 tensor-core GEMM: C[M, NW] = A[M,256] @ B[NW,256]^T, f32 accum.
template <int NW>
__global__ __launch_bounds__(256)
void gemm_kernel(const __half* __restrict__ A,
                 const __half* __restrict__ B,
                 float* __restrict__ C, int M) {
    extern __shared__ __align__(1024) char dsm[];
    const uint32_t sA0 = smem_u32(dsm);
    const uint32_t sB0 = sA0 + 3 * BM * BK * 2;

    int tid = threadIdx.x;
    int lane = tid & 31;
    int wid = tid >> 5;
    int warp_m = wid >> 1;
    int warp_n = wid & 1;
    int bm = blockIdx.y * BM;
    int bn = blockIdx.x * BN;

    int lrow = tid >> 1;
    int lch0 = (tid & 1) * 4;
    int arow_g = bm + lrow;
    int a_ok = (arow_g < M) ? 16 : 0;
    if (arow_g >= M) arow_g = M - 1;
    const char* Ag = (const char*)(A + (long long)arow_g * KTOT) + lch0 * 16;
    const char* Bg = (const char*)(B + (long long)(bn + lrow) * KTOT) + lch0 * 16;
    uint32_t swz[4];
#pragma unroll
    for (int q = 0; q < 4; q++) {
        int ch = lch0 + q;
        swz[q] = (uint32_t)lrow * 128u + (uint32_t)((ch ^ (lrow & 7)) * 16);
    }

    float acc[2][8][4];
#pragma unroll
    for (int i = 0; i < 2; i++)
#pragma unroll
        for (int j = 0; j < 8; j++)
#pragma unroll
            for (int q = 0; q < 4; q++) acc[i][j][q] = 0.f;

    const int NKT = KTOT / BK;   // 4

#pragma unroll
    for (int st = 0; st < 2; st++) {
        uint32_t da = sA0 + st * (BM * BK * 2);
        uint32_t db = sB0 + st * (BN * BK * 2);
        const char* ag = Ag + (long long)st * BK * 2;
        const char* bg = Bg + (long long)st * BK * 2;
#pragma unroll
        for (int q = 0; q < 4; q++) {
            cp16(da + swz[q], ag + q * 16, a_ok);
            cp16(db + swz[q], bg + q * 16, 16);
        }
        asm volatile("cp.async.commit_group;" ::: "memory");
    }

    for (int kt = 0; kt < NKT; kt++) {
        if (kt + 2 < NKT) {
            asm volatile("cp.async.wait_group 1;" ::: "memory");
        } else {
            asm volatile("cp.async.wait_group 0;" ::: "memory");
        }
        __syncthreads();
        if (kt + 2 < NKT) {
            int slot = (kt + 2) % 3;
            uint32_t da = sA0 + slot * (BM * BK * 2);
            uint32_t db = sB0 + slot * (BN * BK * 2);
            const char* ag = Ag + (long long)(kt + 2) * BK * 2;
            const char* bg = Bg + (long long)(kt + 2) * BK * 2;
#pragma unroll
            for (int q = 0; q < 4; q++) {
                cp16(da + swz[q], ag + q * 16, a_ok);
                cp16(db + swz[q], bg + q * 16, 16);
            }
            asm volatile("cp.async.commit_group;" ::: "memory");
        }

        int buf = kt % 3;
        uint32_t abuf = sA0 + buf * (BM * BK * 2);
        uint32_t bbuf = sB0 + buf * (BN * BK * 2);

#pragma unroll
        for (int ks = 0; ks < 4; ks++) {
            uint32_t af[2][4];
#pragma unroll
            for (int mf = 0; mf < 2; mf++) {
                int row = warp_m * 32 + mf * 16 + (lane & 15);
                int ch = ks * 2 + (lane >> 4);
                uint32_t addr = abuf + (uint32_t)row * 128u + (uint32_t)((ch ^ (row & 7)) * 16);
                asm volatile("ldmatrix.sync.aligned.m8n8.x4.shared.b16 {%0,%1,%2,%3}, [%4];"
                             : "=r"(af[mf][0]), "=r"(af[mf][1]), "=r"(af[mf][2]), "=r"(af[mf][3])
                             : "r"(addr));
            }
            uint32_t bfr[8][2];
#pragma unroll
            for (int nb = 0; nb < 4; nb++) {
                int n = warp_n * 64 + nb * 16 + ((lane >> 4) * 8) + (lane & 7);
                int ch = ks * 2 + ((lane >> 3) & 1);
                uint32_t addr = bbuf + (uint32_t)n * 128u + (uint32_t)((ch ^ (n & 7)) * 16);
                uint32_t r0, r1, r2, r3;
                asm volatile("ldmatrix.sync.aligned.m8n8.x4.shared.b16 {%0,%1,%2,%3}, [%4];"
                             : "=r"(r0), "=r"(r1), "=r"(r2), "=r"(r3) : "r"(addr));
                bfr[nb * 2][0] = r0;     bfr[nb * 2][1] = r1;
                bfr[nb * 2 + 1][0] = r2; bfr[nb * 2 + 1][1] = r3;
            }
#pragma unroll
            for (int mf = 0; mf < 2; mf++)
#pragma unroll
                for (int nf = 0; nf < 8; nf++) {
                    asm volatile(
                        "mma.sync.aligned.m16n8k16.row.col.f32.f16.f16.f32 "
                        "{%0,%1,%2,%3}, {%4,%5,%6,%7}, {%8,%9}, {%0,%1,%2,%3};"
                        : "+f"(acc[mf][nf][0]), "+f"(acc[mf][nf][1]),
                          "+f"(acc[mf][nf][2]), "+f"(acc[mf][nf][3])
                        : "r"(af[mf][0]), "r"(af[mf][1]), "r"(af[mf][2]), "r"(af[mf][3]),
                          "r"(bfr[nf][0]), "r"(bfr[nf][1]));
                }
        }
        __syncthreads();
    }

    // plain epilogue: streamed float2 stores
    int g = lane >> 2, tg = lane & 3;
#pragma unroll
    for (int mf = 0; mf < 2; mf++) {
        int row0 = bm + warp_m * 32 + mf * 16 + g;
#pragma unroll
        for (int nf = 0; nf < 8; nf++) {
            int col = bn + warp_n * 64 + nf * 8 + tg * 2;
            if (row0 < M)
                *(float2*)(C + (long long)row0 * NW + col) = make_float2(acc[mf][nf][0], acc[mf][nf][1]);
            if (row0 + 8 < M)
                *(float2*)(C + (long long)(row0 + 8) * NW + col) = make_float2(acc[mf][nf][2], acc[mf][nf][3]);
        }
    }
}

// ---------------------------------------------------------------------------
// gather1: warp per dst node. h1 = b1 + Y[dst, root] + sum_r mean_r;
// then relu + fp16 split -> g_A directly. No atomics, no h1 buffer.
__global__ __launch_bounds__(256)
void gather1_kernel(const float* __restrict__ Y, const float* __restrict__ b1) {
    int n = (int)(((long long)blockIdx.x * blockDim.x + threadIdx.x) >> 5);
    int lane = threadIdx.x & 31;
    if (n >= N_NODES) return;

    // accumulator: root + bias
    float4 acc = *(const float4*)(Y + (long long)n * NW1 + R_REL * 128 + lane * 4);
    float4 bv  = *(const float4*)(b1 + lane * 4);
    acc.x += bv.x; acc.y += bv.y; acc.z += bv.z; acc.w += bv.w;

    int o = (lane < 9) ? g_boff[n * R_REL + lane] : 0;
#pragma unroll
    for (int r = 0; r < R_REL; r++) {
        int s0 = __shfl_sync(0xffffffffu, o, r);
        int s1 = __shfl_sync(0xffffffffu, o, r + 1);
        int cnt = s1 - s0;
        if (cnt == 0) continue;
        float w = 1.0f / (float)cnt;
        float4 sum = make_float4(0.f, 0.f, 0.f, 0.f);
        for (int e = s0; e < s1; e++) {
            int src = g_esrc[e];
            float4 v = *(const float4*)(Y + (long long)src * NW1 + r * 128 + lane * 4);
            sum.x += v.x; sum.y += v.y; sum.z += v.z; sum.w += v.w;
        }
        acc.x += w * sum.x; acc.y += w * sum.y; acc.z += w * sum.z; acc.w += w * sum.w;
    }

    // relu + fp16 split -> g_A
    float vv[4] = {fmaxf(acc.x, 0.f), fmaxf(acc.y, 0.f), fmaxf(acc.z, 0.f), fmaxf(acc.w, 0.f)};
    HF4 hi, lo;
#pragma unroll
    for (int q = 0; q < 4; q++) {
        __half h = __float2half(vv[q]);
        hi.h[q] = h;
        lo.h[q] = __float2half(vv[q] - __half2float(h));
    }
    __half* row = g_A + (long long)n * KTOT;
    *(uint2*)(row + lane * 4)       = hi.u;
    *(uint2*)(row + 128 + lane * 4) = lo.u;
}

// gather2: warp per dst node, fused classifier. logits = relu(h2) @ Wc + bc.
__global__ __launch_bounds__(256)
void gather2_kernel(const float* __restrict__ Y, const float* __restrict__ b2,
                    const float* __restrict__ Wc, const float* __restrict__ bc,
                    float* __restrict__ out) {
    int n = (int)(((long long)blockIdx.x * blockDim.x + threadIdx.x) >> 5);
    int lane = threadIdx.x & 31;
    if (n >= N_NODES) return;

    float2 acc = *(const float2*)(Y + (long long)n * NW2 + R_REL * 64 + lane * 2);
    float2 bv  = *(const float2*)(b2 + lane * 2);
    acc.x += bv.x; acc.y += bv.y;

    int o = (lane < 9) ? g_boff[n * R_REL + lane] : 0;
#pragma unroll
    for (int r = 0; r < R_REL; r++) {
        int s0 = __shfl_sync(0xffffffffu, o, r);
        int s1 = __shfl_sync(0xffffffffu, o, r + 1);
        int cnt = s1 - s0;
        if (cnt == 0) continue;
        float w = 1.0f / (float)cnt;
        float2 sum = make_float2(0.f, 0.f);
        for (int e = s0; e < s1; e++) {
            int src = g_esrc[e];
            float2 v = *(const float2*)(Y + (long long)src * NW2 + r * 64 + lane * 2);
            sum.x += v.x; sum.y += v.y;
        }
        acc.x += w * sum.x; acc.y += w * sum.y;
    }

    // relu + classifier: lane covers features 2*lane, 2*lane+1
    float vx = fmaxf(acc.x, 0.f), vy = fmaxf(acc.y, 0.f);
    float4 w4 = *(const float4*)(Wc + lane * 4);   // Wc[2l][0],Wc[2l][1],Wc[2l+1][0],Wc[2l+1][1]
    float a0 = vx * w4.x + vy * w4.z;
    float a1 = vx * w4.y + vy * w4.w;
#pragma unroll
    for (int off = 16; off; off >>= 1) {
        a0 += __shfl_down_sync(0xffffffffu, a0, off);
        a1 += __shfl_down_sync(0xffffffffu, a1, off);
    }
    if (lane == 0) {
        out[n * 2 + 0] = a0 + bc[0];
        out[n * 2 + 1] = a1 + bc[1];
    }
}

// ---------------------------------------------------------------------------
extern "C" void kernel_launch(void* const* d_in, const int* in_sizes, int n_in,
                              void* d_out, int out_size) {
    const float* x     = (const float*)d_in[0];
    const int*   eidx  = (const int*)d_in[1];
    const int*   etype = (const int*)d_in[2];
    const float* W1    = (const float*)d_in[3];
    const float* root1 = (const float*)d_in[4];
    const float* b1    = (const float*)d_in[5];
    const float* W2    = (const float*)d_in[6];
    const float* root2 = (const float*)d_in[7];
    const float* b2    = (const float*)d_in[8];
    const float* Wc    = (const float*)d_in[9];
    const float* bc    = (const float*)d_in[10];
    float* logits = (float*)d_out;

    const int* src = eidx;
    const int* dst = eidx + N_EDGES;

    float* Yp;  cudaGetSymbolAddress((void**)&Yp, g_Y);
    __half* Ap;  cudaGetSymbolAddress((void**)&Ap, g_A);
    __half* B1p; cudaGetSymbolAddress((void**)&B1p, g_B1);
    __half* B2p; cudaGetSymbolAddress((void**)&B2p, g_B2);
    int* scp; cudaGetSymbolAddress((void**)&scp, g_segcnt);

    const int GEMM_SMEM = 3 * 2 * BM * BK * 2;   // 96KB
    static int attr_done = 0;
    if (!attr_done) {
        cudaFuncSetAttribute(gemm_kernel<NW1>, cudaFuncAttributeMaxDynamicSharedMemorySize, GEMM_SMEM);
        cudaFuncSetAttribute(gemm_kernel<NW2>, cudaFuncAttributeMaxDynamicSharedMemorySize, GEMM_SMEM);
        attr_done = 1;
    }

    // CSR build
    cudaMemsetAsync(scp, 0, NSEG * sizeof(int));
    count_kernel<<<N_EDGES / 1024, 256>>>(src, dst, etype);
    scan_reduce_kernel<<<NCH, SCH>>>();
    scan_block_kernel<<<1, 1024>>>();
    scan_final_kernel<<<NCH, SCH>>>();
    fill_kernel<<<N_EDGES / 1024, 256>>>(src, dst, etype);

    // prep (A split + W splits)
    {
        long long total = PV_A1 + PS_W1 + PS_W2;
        prep_kernel<<<(int)((total + 255) / 256), 256>>>(x, W1, root1, W2, root2);
    }

    // layer 1: GEMM -> Y, gather -> g_A (relu+split fused)
    {
        dim3 grid(NW1 / BN, (N_NODES + BM - 1) / BM);
        gemm_kernel<NW1><<<grid, 256, GEMM_SMEM>>>(Ap, B1p, Yp, N_NODES);
    }
    gather1_kernel<<<(N_NODES * 32 + 255) / 256, 256>>>(Yp, b1);

    // layer 2: GEMM -> Y, gather+classifier -> logits
    {
        dim3 grid(NW2 / BN, (N_NODES + BM - 1) / BM);
        gemm_kernel<NW2><<<grid, 256, GEMM_SMEM>>>(Ap, B2p, Yp, N_NODES);
    }
    gather2_kernel<<<(N_NODES * 32 + 255) / 256, 256>>>(Yp, b2, Wc, bc, logits);
}

// round 8
// speedup vs baseline: 1.6107x; 1.0379x over previous
#include <cuda_runtime.h>
#include <cuda_fp16.h>
#include <cstdint>

// Problem constants
#define N_NODES 50000
#define N_EDGES 640000
#define R_REL   8
#define NSEG    (N_NODES * R_REL)   // 400000 segments, key = dst*8+rel
#define NW1     1152                // (R+1)*128
#define NW2     640                 // (R+1)*64 = 576 padded to 640
#define KTOT    256                 // [Ah|Al] fp16 2-term split K

#define BM 128
#define BN 128
#define BK 64

// scan config
#define SCH  512
#define NCH  ((NSEG + SCH - 1) / SCH)  // 782

// ---------------------------------------------------------------------------
// Device scratch
__device__ __half g_Y[(long long)N_NODES * NW1];   // GEMM out, fp16 (layer-reused)
__device__ int    g_segcnt[NSEG];
__device__ int    g_bsum[NCH];
__device__ int    g_bsum_ex[NCH];
__device__ int    g_boff[NSEG + 1];
__device__ int    g_bcur[NSEG];
__device__ int    g_esrc[N_EDGES];
__device__ __half g_A[(long long)N_NODES * KTOT];
__device__ __half g_B1[NW1 * KTOT];
__device__ __half g_B2[NW2 * KTOT];

__device__ __forceinline__ uint32_t smem_u32(const void* p) {
    uint32_t a;
    asm("{ .reg .u64 t; cvta.to.shared.u64 t, %1; cvt.u32.u64 %0, t; }" : "=r"(a) : "l"(p));
    return a;
}
__device__ __forceinline__ void cp16(uint32_t dst, const void* src, int src_sz) {
    asm volatile("cp.async.cg.shared.global [%0], [%1], 16, %2;"
                 :: "r"(dst), "l"(src), "r"(src_sz));
}
union HF4 { __half h[4]; uint2 u; };

// ---------------------------------------------------------------------------
// (1) per-segment histogram, 4 edges/thread
__global__ void count_kernel(const int* __restrict__ src, const int* __restrict__ dst,
                             const int* __restrict__ etype) {
    int e0 = (blockIdx.x * blockDim.x + threadIdx.x) * 4;
    if (e0 >= N_EDGES) return;
    int t[4], d[4];
#pragma unroll
    for (int q = 0; q < 4; q++) { t[q] = etype[e0 + q]; d[q] = dst[e0 + q]; }
#pragma unroll
    for (int q = 0; q < 4; q++) atomicAdd(&g_segcnt[d[q] * R_REL + t[q]], 1);
}

// (2a) per-chunk reduce
__global__ void scan_reduce_kernel() {
    __shared__ int sh[SCH];
    int i = blockIdx.x * SCH + threadIdx.x;
    sh[threadIdx.x] = (i < NSEG) ? g_segcnt[i] : 0;
    __syncthreads();
    for (int off = SCH / 2; off > 0; off >>= 1) {
        if (threadIdx.x < off) sh[threadIdx.x] += sh[threadIdx.x + off];
        __syncthreads();
    }
    if (threadIdx.x == 0) g_bsum[blockIdx.x] = sh[0];
}

// (2b) scan chunk sums
__global__ void scan_block_kernel() {
    __shared__ int sh[1024];
    int t = threadIdx.x;
    int v = (t < NCH) ? g_bsum[t] : 0;
    sh[t] = v;
    __syncthreads();
    for (int off = 1; off < 1024; off <<= 1) {
        int tv = (t >= off) ? sh[t - off] : 0;
        __syncthreads();
        sh[t] += tv;
        __syncthreads();
    }
    if (t < NCH) g_bsum_ex[t] = sh[t] - v;
    if (t == 1023) g_boff[NSEG] = sh[t];
}

// (2c) per-chunk exclusive scan -> boff, bcur
__global__ void scan_final_kernel() {
    __shared__ int sh[SCH];
    int i = blockIdx.x * SCH + threadIdx.x;
    int v = (i < NSEG) ? g_segcnt[i] : 0;
    sh[threadIdx.x] = v;
    __syncthreads();
    for (int off = 1; off < SCH; off <<= 1) {
        int tv = (threadIdx.x >= off) ? sh[threadIdx.x - off] : 0;
        __syncthreads();
        sh[threadIdx.x] += tv;
        __syncthreads();
    }
    if (i < NSEG) {
        int ex = sh[threadIdx.x] - v + g_bsum_ex[blockIdx.x];
        g_boff[i] = ex;
        g_bcur[i] = ex;
    }
}

// (3) segment-sorted edge source array
__global__ void fill_kernel(const int* __restrict__ src, const int* __restrict__ dst,
                            const int* __restrict__ etype) {
    int e0 = (blockIdx.x * blockDim.x + threadIdx.x) * 4;
    if (e0 >= N_EDGES) return;
    int s[4], d[4], t[4];
#pragma unroll
    for (int q = 0; q < 4; q++) {
        s[q] = src[e0 + q]; d[q] = dst[e0 + q]; t[q] = etype[e0 + q];
    }
#pragma unroll
    for (int q = 0; q < 4; q++) {
        int pos = atomicAdd(&g_bcur[d[q] * R_REL + t[q]], 1);
        g_esrc[pos] = s[q];
    }
}

// (4) prep: A1 fp16 split (vec4) + W1/W2 splits (scalar)
#define PV_A1 1600000LL
#define PS_W1 147456LL
#define PS_W2 81920LL
__global__ void prep_kernel(const float* __restrict__ x,
                            const float* __restrict__ W1, const float* __restrict__ root1,
                            const float* __restrict__ W2, const float* __restrict__ root2) {
    long long i = (long long)blockIdx.x * blockDim.x + threadIdx.x;
    if (i < PV_A1) {
        int n = (int)(i >> 5), j = (int)(i & 31) * 4;
        float4 v = *(const float4*)(x + (long long)n * 128 + j);
        HF4 hi, lo;
        float vv[4] = {v.x, v.y, v.z, v.w};
#pragma unroll
        for (int q = 0; q < 4; q++) {
            __half h = __float2half(vv[q]);
            hi.h[q] = h;
            lo.h[q] = __float2half(vv[q] - __half2float(h));
        }
        __half* row = g_A + (long long)n * KTOT;
        *(uint2*)(row + j)       = hi.u;
        *(uint2*)(row + 128 + j) = lo.u;
        return;
    }
    i -= PV_A1;
    if (i < PS_W1) {
        int n = (int)(i >> 7), k = (int)(i & 127);
        float v;
        if (n < R_REL * 128) {
            int r = n >> 7, o = n & 127;
            v = W1[((long long)r * 128 + k) * 128 + o];
        } else {
            v = root1[k * 128 + (n - R_REL * 128)];
        }
        __half h = __float2half(v);
        __half* row = g_B1 + (long long)n * KTOT;
        row[k] = h; row[128 + k] = h;
        return;
    }
    i -= PS_W1;
    if (i < PS_W2) {
        int n = (int)(i >> 7), k = (int)(i & 127);
        float v = 0.f;
        if (n < R_REL * 64) {
            int r = n >> 6, o = n & 63;
            v = W2[((long long)r * 128 + k) * 64 + o];
        } else if (n < 576) {
            v = root2[k * 64 + (n - R_REL * 64)];
        }
        __half h = __float2half(v);
        __half* row = g_B2 + (long long)n * KTOT;
        row[k] = h; row[128 + k] = h;
    }
}

// ---------------------------------------------------------------------------
// fp16 tensor-core GEMM: C[M, NW] = A[M,256] @ B[NW,256]^T, f32 accum, fp16 out.
template <int NW>
__global__ __launch_bounds__(256)
void gemm_kernel(const __half* __restrict__ A,
                 const __half* __restrict__ B,
                 __half* __restrict__ C, int M) {
    extern __shared__ __align__(1024) char dsm[];
    const uint32_t sA0 = smem_u32(dsm);
    const uint32_t sB0 = sA0 + 3 * BM * BK * 2;

    int tid = threadIdx.x;
    int lane = tid & 31;
    int wid = tid >> 5;
    int warp_m = wid >> 1;
    int warp_n = wid & 1;
    int bm = blockIdx.y * BM;
    int bn = blockIdx.x * BN;

    int lrow = tid >> 1;
    int lch0 = (tid & 1) * 4;
    int arow_g = bm + lrow;
    int a_ok = (arow_g < M) ? 16 : 0;
    if (arow_g >= M) arow_g = M - 1;
    const char* Ag = (const char*)(A + (long long)arow_g * KTOT) + lch0 * 16;
    const char* Bg = (const char*)(B + (long long)(bn + lrow) * KTOT) + lch0 * 16;
    uint32_t swz[4];
#pragma unroll
    for (int q = 0; q < 4; q++) {
        int ch = lch0 + q;
        swz[q] = (uint32_t)lrow * 128u + (uint32_t)((ch ^ (lrow & 7)) * 16);
    }

    float acc[2][8][4];
#pragma unroll
    for (int i = 0; i < 2; i++)
#pragma unroll
        for (int j = 0; j < 8; j++)
#pragma unroll
            for (int q = 0; q < 4; q++) acc[i][j][q] = 0.f;

    const int NKT = KTOT / BK;   // 4

#pragma unroll
    for (int st = 0; st < 2; st++) {
        uint32_t da = sA0 + st * (BM * BK * 2);
        uint32_t db = sB0 + st * (BN * BK * 2);
        const char* ag = Ag + (long long)st * BK * 2;
        const char* bg = Bg + (long long)st * BK * 2;
#pragma unroll
        for (int q = 0; q < 4; q++) {
            cp16(da + swz[q], ag + q * 16, a_ok);
            cp16(db + swz[q], bg + q * 16, 16);
        }
        asm volatile("cp.async.commit_group;" ::: "memory");
    }

    for (int kt = 0; kt < NKT; kt++) {
        if (kt + 2 < NKT) {
            asm volatile("cp.async.wait_group 1;" ::: "memory");
        } else {
            asm volatile("cp.async.wait_group 0;" ::: "memory");
        }
        __syncthreads();
        if (kt + 2 < NKT) {
            int slot = (kt + 2) % 3;
            uint32_t da = sA0 + slot * (BM * BK * 2);
            uint32_t db = sB0 + slot * (BN * BK * 2);
            const char* ag = Ag + (long long)(kt + 2) * BK * 2;
            const char* bg = Bg + (long long)(kt + 2) * BK * 2;
#pragma unroll
            for (int q = 0; q < 4; q++) {
                cp16(da + swz[q], ag + q * 16, a_ok);
                cp16(db + swz[q], bg + q * 16, 16);
            }
            asm volatile("cp.async.commit_group;" ::: "memory");
        }

        int buf = kt % 3;
        uint32_t abuf = sA0 + buf * (BM * BK * 2);
        uint32_t bbuf = sB0 + buf * (BN * BK * 2);

#pragma unroll
        for (int ks = 0; ks < 4; ks++) {
            uint32_t af[2][4];
#pragma unroll
            for (int mf = 0; mf < 2; mf++) {
                int row = warp_m * 32 + mf * 16 + (lane & 15);
                int ch = ks * 2 + (lane >> 4);
                uint32_t addr = abuf + (uint32_t)row * 128u + (uint32_t)((ch ^ (row & 7)) * 16);
                asm volatile("ldmatrix.sync.aligned.m8n8.x4.shared.b16 {%0,%1,%2,%3}, [%4];"
                             : "=r"(af[mf][0]), "=r"(af[mf][1]), "=r"(af[mf][2]), "=r"(af[mf][3])
                             : "r"(addr));
            }
            uint32_t bfr[8][2];
#pragma unroll
            for (int nb = 0; nb < 4; nb++) {
                int n = warp_n * 64 + nb * 16 + ((lane >> 4) * 8) + (lane & 7);
                int ch = ks * 2 + ((lane >> 3) & 1);
                uint32_t addr = bbuf + (uint32_t)n * 128u + (uint32_t)((ch ^ (n & 7)) * 16);
                uint32_t r0, r1, r2, r3;
                asm volatile("ldmatrix.sync.aligned.m8n8.x4.shared.b16 {%0,%1,%2,%3}, [%4];"
                             : "=r"(r0), "=r"(r1), "=r"(r2), "=r"(r3) : "r"(addr));
                bfr[nb * 2][0] = r0;     bfr[nb * 2][1] = r1;
                bfr[nb * 2 + 1][0] = r2; bfr[nb * 2 + 1][1] = r3;
            }
#pragma unroll
            for (int mf = 0; mf < 2; mf++)
#pragma unroll
                for (int nf = 0; nf < 8; nf++) {
                    asm volatile(
                        "mma.sync.aligned.m16n8k16.row.col.f32.f16.f16.f32 "
                        "{%0,%1,%2,%3}, {%4,%5,%6,%7}, {%8,%9}, {%0,%1,%2,%3};"
                        : "+f"(acc[mf][nf][0]), "+f"(acc[mf][nf][1]),
                          "+f"(acc[mf][nf][2]), "+f"(acc[mf][nf][3])
                        : "r"(af[mf][0]), "r"(af[mf][1]), "r"(af[mf][2]), "r"(af[mf][3]),
                          "r"(bfr[nf][0]), "r"(bfr[nf][1]));
                }
        }
        __syncthreads();
    }

    // epilogue: fp16 half2 stores
    int g = lane >> 2, tg = lane & 3;
#pragma unroll
    for (int mf = 0; mf < 2; mf++) {
        int row0 = bm + warp_m * 32 + mf * 16 + g;
#pragma unroll
        for (int nf = 0; nf < 8; nf++) {
            int col = bn + warp_n * 64 + nf * 8 + tg * 2;
            if (row0 < M)
                *(__half2*)(C + (long long)row0 * NW + col) =
                    __floats2half2_rn(acc[mf][nf][0], acc[mf][nf][1]);
            if (row0 + 8 < M)
                *(__half2*)(C + (long long)(row0 + 8) * NW + col) =
                    __floats2half2_rn(acc[mf][nf][2], acc[mf][nf][3]);
        }
    }
}

// ---------------------------------------------------------------------------
// gather1: warp per dst node, fp16 Y. h1 = b1 + Y[dst,root] + sum_r mean_r;
// relu + fp16 split -> g_A directly.
__global__ __launch_bounds__(256)
void gather1_kernel(const __half* __restrict__ Y, const float* __restrict__ b1) {
    int n = (int)(((long long)blockIdx.x * blockDim.x + threadIdx.x) >> 5);
    int lane = threadIdx.x & 31;
    if (n >= N_NODES) return;

    // accumulator: root + bias (lane covers features 4l..4l+3)
    float accv[4];
    {
        uint2 raw = *(const uint2*)(Y + (long long)n * NW1 + R_REL * 128 + lane * 4);
        float2 f0 = __half22float2(*(__half2*)&raw.x);
        float2 f1 = __half22float2(*(__half2*)&raw.y);
        float4 bv = *(const float4*)(b1 + lane * 4);
        accv[0] = f0.x + bv.x; accv[1] = f0.y + bv.y;
        accv[2] = f1.x + bv.z; accv[3] = f1.y + bv.w;
    }

    int o = (lane < 9) ? g_boff[n * R_REL + lane] : 0;
#pragma unroll
    for (int r = 0; r < R_REL; r++) {
        int s0 = __shfl_sync(0xffffffffu, o, r);
        int s1 = __shfl_sync(0xffffffffu, o, r + 1);
        int cnt = s1 - s0;
        if (cnt == 0) continue;
        float w = 1.0f / (float)cnt;
        float sum[4] = {0.f, 0.f, 0.f, 0.f};
        for (int e = s0; e < s1; e++) {
            int src = g_esrc[e];
            uint2 raw = *(const uint2*)(Y + (long long)src * NW1 + r * 128 + lane * 4);
            float2 f0 = __half22float2(*(__half2*)&raw.x);
            float2 f1 = __half22float2(*(__half2*)&raw.y);
            sum[0] += f0.x; sum[1] += f0.y; sum[2] += f1.x; sum[3] += f1.y;
        }
#pragma unroll
        for (int q = 0; q < 4; q++) accv[q] += w * sum[q];
    }

    // relu + fp16 split -> g_A
    HF4 hi, lo;
#pragma unroll
    for (int q = 0; q < 4; q++) {
        float v = fmaxf(accv[q], 0.f);
        __half h = __float2half(v);
        hi.h[q] = h;
        lo.h[q] = __float2half(v - __half2float(h));
    }
    __half* row = g_A + (long long)n * KTOT;
    *(uint2*)(row + lane * 4)       = hi.u;
    *(uint2*)(row + 128 + lane * 4) = lo.u;
}

// gather2: warp per dst node, fp16 Y, fused classifier.
__global__ __launch_bounds__(256)
void gather2_kernel(const __half* __restrict__ Y, const float* __restrict__ b2,
                    const float* __restrict__ Wc, const float* __restrict__ bc,
                    float* __restrict__ out) {
    int n = (int)(((long long)blockIdx.x * blockDim.x + threadIdx.x) >> 5);
    int lane = threadIdx.x & 31;
    if (n >= N_NODES) return;

    float ax, ay;
    {
        __half2 rv = *(const __half2*)(Y + (long long)n * NW2 + R_REL * 64 + lane * 2);
        float2 f = __half22float2(rv);
        float2 bv = *(const float2*)(b2 + lane * 2);
        ax = f.x + bv.x; ay = f.y + bv.y;
    }

    int o = (lane < 9) ? g_boff[n * R_REL + lane] : 0;
#pragma unroll
    for (int r = 0; r < R_REL; r++) {
        int s0 = __shfl_sync(0xffffffffu, o, r);
        int s1 = __shfl_sync(0xffffffffu, o, r + 1);
        int cnt = s1 - s0;
        if (cnt == 0) continue;
        float w = 1.0f / (float)cnt;
        float sx = 0.f, sy = 0.f;
        for (int e = s0; e < s1; e++) {
            int src = g_esrc[e];
            __half2 v = *(const __half2*)(Y + (long long)src * NW2 + r * 64 + lane * 2);
            float2 f = __half22float2(v);
            sx += f.x; sy += f.y;
        }
        ax += w * sx; ay += w * sy;
    }

    // relu + classifier: lane covers features 2l, 2l+1
    float vx = fmaxf(ax, 0.f), vy = fmaxf(ay, 0.f);
    float4 w4 = *(const float4*)(Wc + lane * 4);
    float a0 = vx * w4.x + vy * w4.z;
    float a1 = vx * w4.y + vy * w4.w;
#pragma unroll
    for (int off = 16; off; off >>= 1) {
        a0 += __shfl_down_sync(0xffffffffu, a0, off);
        a1 += __shfl_down_sync(0xffffffffu, a1, off);
    }
    if (lane == 0) {
        out[n * 2 + 0] = a0 + bc[0];
        out[n * 2 + 1] = a1 + bc[1];
    }
}

// ---------------------------------------------------------------------------
extern "C" void kernel_launch(void* const* d_in, const int* in_sizes, int n_in,
                              void* d_out, int out_size) {
    const float* x     = (const float*)d_in[0];
    const int*   eidx  = (const int*)d_in[1];
    const int*   etype = (const int*)d_in[2];
    const float* W1    = (const float*)d_in[3];
    const float* root1 = (const float*)d_in[4];
    const float* b1    = (const float*)d_in[5];
    const float* W2    = (const float*)d_in[6];
    const float* root2 = (const float*)d_in[7];
    const float* b2    = (const float*)d_in[8];
    const float* Wc    = (const float*)d_in[9];
    const float* bc    = (const float*)d_in[10];
    float* logits = (float*)d_out;

    const int* src = eidx;
    const int* dst = eidx + N_EDGES;

    __half* Yp;  cudaGetSymbolAddress((void**)&Yp, g_Y);
    __half* Ap;  cudaGetSymbolAddress((void**)&Ap, g_A);
    __half* B1p; cudaGetSymbolAddress((void**)&B1p, g_B1);
    __half* B2p; cudaGetSymbolAddress((void**)&B2p, g_B2);
    int* scp; cudaGetSymbolAddress((void**)&scp, g_segcnt);

    const int GEMM_SMEM = 3 * 2 * BM * BK * 2;   // 96KB
    static int attr_done = 0;
    if (!attr_done) {
        cudaFuncSetAttribute(gemm_kernel<NW1>, cudaFuncAttributeMaxDynamicSharedMemorySize, GEMM_SMEM);
        cudaFuncSetAttribute(gemm_kernel<NW2>, cudaFuncAttributeMaxDynamicSharedMemorySize, GEMM_SMEM);
        attr_done = 1;
    }

    // CSR build
    cudaMemsetAsync(scp, 0, NSEG * sizeof(int));
    count_kernel<<<N_EDGES / 1024, 256>>>(src, dst, etype);
    scan_reduce_kernel<<<NCH, SCH>>>();
    scan_block_kernel<<<1, 1024>>>();
    scan_final_kernel<<<NCH, SCH>>>();
    fill_kernel<<<N_EDGES / 1024, 256>>>(src, dst, etype);

    // prep (A split + W splits)
    {
        long long total = PV_A1 + PS_W1 + PS_W2;
        prep_kernel<<<(int)((total + 255) / 256), 256>>>(x, W1, root1, W2, root2);
    }

    // layer 1: GEMM -> Y(fp16), gather -> g_A (relu+split fused)
    {
        dim3 grid(NW1 / BN, (N_NODES + BM - 1) / BM);
        gemm_kernel<NW1><<<grid, 256, GEMM_SMEM>>>(Ap, B1p, Yp, N_NODES);
    }
    gather1_kernel<<<(N_NODES * 32 + 255) / 256, 256>>>(Yp, b1);

    // layer 2: GEMM -> Y(fp16), gather+classifier -> logits
    {
        dim3 grid(NW2 / BN, (N_NODES + BM - 1) / BM);
        gemm_kernel<NW2><<<grid, 256, GEMM_SMEM>>>(Ap, B2p, Yp, N_NODES);
    }
    gather2_kernel<<<(N_NODES * 32 + 255) / 256, 256>>>(Yp, b2, Wc, bc, logits);
}